// round 1
// baseline (speedup 1.0000x reference)
#include <cuda_runtime.h>
#include <cuda_bf16.h>
#include <math.h>

// ---------------------------------------------------------------------------
// Problem constants
// ---------------------------------------------------------------------------
#define BATCH   4
#define SEQ     2048
#define EMBED   1024
#define HEADS   8
#define HDIM    128            // EMBED / HEADS
#define MROWS   (BATCH * SEQ)  // 8192
#define QKV_N   (3 * EMBED)    // 3072

// Scratch: __device__ globals (no allocation allowed anywhere)
__device__ float g_qkv[(size_t)BATCH * SEQ * QKV_N];   // [B,N,3D]
__device__ float g_att[(size_t)BATCH * SEQ * EMBED];   // [B,N,D] merged-head attn out

// ---------------------------------------------------------------------------
// SGEMM with bias: C[M,N] = A[M,K] @ B[K,N] + bias[N]
// 128x128 block tile, K-tile 8, 256 threads, 8x8 per-thread microtile.
// M,N multiples of 128; K multiple of 8 (holds for all our shapes).
// ---------------------------------------------------------------------------
__global__ __launch_bounds__(256, 2)
void sgemm_bias_kernel(const float* __restrict__ A, const float* __restrict__ B,
                       const float* __restrict__ bias, float* __restrict__ C,
                       int M, int N, int K)
{
    __shared__ float As[8][128];   // As[kk][row]  (A tile transposed)
    __shared__ float Bs[8][128];   // Bs[kk][col]

    const int tid = threadIdx.x;
    const int bm = blockIdx.y * 128;
    const int bn = blockIdx.x * 128;
    const int tx = tid & 15;       // 16 col-groups
    const int ty = tid >> 4;       // 16 row-groups

    const int a_row = tid >> 1;          // 0..127
    const int a_col = (tid & 1) * 4;     // 0 or 4
    const int b_row = tid >> 5;          // 0..7
    const int b_col = (tid & 31) * 4;    // 0..124

    const float* Ap = A + (size_t)(bm + a_row) * K + a_col;
    const float* Bp = B + (size_t)b_row * N + bn + b_col;

    float acc[8][8];
#pragma unroll
    for (int i = 0; i < 8; i++)
#pragma unroll
        for (int j = 0; j < 8; j++) acc[i][j] = 0.f;

    for (int k0 = 0; k0 < K; k0 += 8) {
        float4 av = *reinterpret_cast<const float4*>(Ap + k0);
        float4 bv = *reinterpret_cast<const float4*>(Bp + (size_t)k0 * N);
        As[a_col + 0][a_row] = av.x;
        As[a_col + 1][a_row] = av.y;
        As[a_col + 2][a_row] = av.z;
        As[a_col + 3][a_row] = av.w;
        *reinterpret_cast<float4*>(&Bs[b_row][b_col]) = bv;
        __syncthreads();

#pragma unroll
        for (int kk = 0; kk < 8; kk++) {
            float4 a0 = *reinterpret_cast<const float4*>(&As[kk][ty * 4]);
            float4 a1 = *reinterpret_cast<const float4*>(&As[kk][64 + ty * 4]);
            float4 b0 = *reinterpret_cast<const float4*>(&Bs[kk][tx * 4]);
            float4 b1 = *reinterpret_cast<const float4*>(&Bs[kk][64 + tx * 4]);
            float ar[8] = {a0.x, a0.y, a0.z, a0.w, a1.x, a1.y, a1.z, a1.w};
            float br[8] = {b0.x, b0.y, b0.z, b0.w, b1.x, b1.y, b1.z, b1.w};
#pragma unroll
            for (int i = 0; i < 8; i++)
#pragma unroll
                for (int j = 0; j < 8; j++)
                    acc[i][j] = fmaf(ar[i], br[j], acc[i][j]);
        }
        __syncthreads();
    }

    // epilogue
    float4 bi0 = *reinterpret_cast<const float4*>(&bias[bn + tx * 4]);
    float4 bi1 = *reinterpret_cast<const float4*>(&bias[bn + 64 + tx * 4]);
#pragma unroll
    for (int i = 0; i < 8; i++) {
        int rl = (i < 4) ? (ty * 4 + i) : (64 + ty * 4 + (i - 4));
        float* Crow = C + (size_t)(bm + rl) * N + bn;
        float4 o0, o1;
        o0.x = acc[i][0] + bi0.x; o0.y = acc[i][1] + bi0.y;
        o0.z = acc[i][2] + bi0.z; o0.w = acc[i][3] + bi0.w;
        o1.x = acc[i][4] + bi1.x; o1.y = acc[i][5] + bi1.y;
        o1.z = acc[i][6] + bi1.z; o1.w = acc[i][7] + bi1.w;
        *reinterpret_cast<float4*>(Crow + tx * 4) = o0;
        *reinterpret_cast<float4*>(Crow + 64 + tx * 4) = o1;
    }
}

// ---------------------------------------------------------------------------
// Flash attention (fp32, online softmax).
// Grid: (SEQ/64, HEADS, BATCH), 256 threads.
// Q tile = 64 rows x 128 (full head dim), K/V tiles = 64 rows.
// Smem (floats): Qs[128][68] d-major, Ks[128][68] d-major, Vs[64][128],
//                Ss[64][68], m/l/corr[64] each.
// ---------------------------------------------------------------------------
#define QS_OFF   0
#define KS_OFF   (128 * 68)                 // 8704
#define VS_OFF   (KS_OFF + 128 * 68)        // 17408
#define SS_OFF   (VS_OFF + 64 * 128)        // 25600
#define MS_OFF   (SS_OFF + 64 * 68)         // 29952
#define LS_OFF   (MS_OFF + 64)
#define CS_OFF   (LS_OFF + 64)
#define FA_SMEM_FLOATS (CS_OFF + 64)        // 30144
#define FA_SMEM_BYTES  (FA_SMEM_FLOATS * 4) // 120576 B

__global__ __launch_bounds__(256, 1)
void attention_kernel(const float* __restrict__ qkv, float* __restrict__ out)
{
    extern __shared__ float sm[];
    float* Qs  = sm + QS_OFF;
    float* Ks  = sm + KS_OFF;
    float* Vs  = sm + VS_OFF;
    float* Ss  = sm + SS_OFF;
    float* m_s = sm + MS_OFF;
    float* l_s = sm + LS_OFF;
    float* c_s = sm + CS_OFF;

    const int tid  = threadIdx.x;
    const int lane = tid & 31;
    const int warp = tid >> 5;
    const int tx   = tid & 15;
    const int ty   = tid >> 4;
    const int q0   = blockIdx.x * 64;
    const int h    = blockIdx.y;
    const int b    = blockIdx.z;

    const size_t base = (size_t)b * SEQ * QKV_N + (size_t)h * HDIM;
    const float* Qg = qkv + base;                // + row*QKV_N
    const float* Kg = qkv + base + EMBED;
    const float* Vg = qkv + base + 2 * EMBED;

    // ---- load Q tile transposed: Qs[d][qi] ----
    {
        const int d4 = (tid & 31) * 4;
#pragma unroll
        for (int pass = 0; pass < 8; pass++) {
            int qi = pass * 8 + warp;
            float4 v = *reinterpret_cast<const float4*>(
                Qg + (size_t)(q0 + qi) * QKV_N + d4);
            Qs[(d4 + 0) * 68 + qi] = v.x;
            Qs[(d4 + 1) * 68 + qi] = v.y;
            Qs[(d4 + 2) * 68 + qi] = v.z;
            Qs[(d4 + 3) * 68 + qi] = v.w;
        }
    }
    if (tid < 64) { m_s[tid] = -1e30f; l_s[tid] = 0.f; }

    float o[4][8];
#pragma unroll
    for (int i = 0; i < 4; i++)
#pragma unroll
        for (int j = 0; j < 8; j++) o[i][j] = 0.f;

    const float sc = 0.08838834764831845f;   // 128^-0.5

    for (int kt = 0; kt < SEQ / 64; kt++) {
        // ---- load K tile transposed, V tile row-major ----
        {
            const int d4 = (tid & 31) * 4;
#pragma unroll
            for (int pass = 0; pass < 8; pass++) {
                int ki = pass * 8 + warp;
                size_t grow = (size_t)(kt * 64 + ki) * QKV_N + d4;
                float4 kv = *reinterpret_cast<const float4*>(Kg + grow);
                Ks[(d4 + 0) * 68 + ki] = kv.x;
                Ks[(d4 + 1) * 68 + ki] = kv.y;
                Ks[(d4 + 2) * 68 + ki] = kv.z;
                Ks[(d4 + 3) * 68 + ki] = kv.w;
                float4 vv = *reinterpret_cast<const float4*>(Vg + grow);
                *reinterpret_cast<float4*>(&Vs[ki * 128 + d4]) = vv;
            }
        }
        __syncthreads();

        // ---- S = (Q^T K) tile: each thread 4x4 at rows ty*4.., cols tx*4.. ----
        float s[4][4];
#pragma unroll
        for (int i = 0; i < 4; i++)
#pragma unroll
            for (int j = 0; j < 4; j++) s[i][j] = 0.f;

#pragma unroll 4
        for (int kk = 0; kk < 128; kk++) {
            float4 qv = *reinterpret_cast<const float4*>(&Qs[kk * 68 + ty * 4]);
            float4 kv = *reinterpret_cast<const float4*>(&Ks[kk * 68 + tx * 4]);
            float qr[4] = {qv.x, qv.y, qv.z, qv.w};
            float kr[4] = {kv.x, kv.y, kv.z, kv.w};
#pragma unroll
            for (int i = 0; i < 4; i++)
#pragma unroll
                for (int j = 0; j < 4; j++)
                    s[i][j] = fmaf(qr[i], kr[j], s[i][j]);
        }
#pragma unroll
        for (int i = 0; i < 4; i++) {
            float4 v;
            v.x = s[i][0] * sc; v.y = s[i][1] * sc;
            v.z = s[i][2] * sc; v.w = s[i][3] * sc;
            *reinterpret_cast<float4*>(&Ss[(ty * 4 + i) * 68 + tx * 4]) = v;
        }
        __syncthreads();

        // ---- online softmax: warp w owns rows w*8..w*8+7 ----
#pragma unroll
        for (int rr = 0; rr < 8; rr++) {
            int r = warp * 8 + rr;
            float x0 = Ss[r * 68 + lane];
            float x1 = Ss[r * 68 + 32 + lane];
            float mx = fmaxf(x0, x1);
#pragma unroll
            for (int off = 16; off > 0; off >>= 1)
                mx = fmaxf(mx, __shfl_xor_sync(0xffffffffu, mx, off));
            float mo = m_s[r];
            float M  = fmaxf(mo, mx);
            float p0 = __expf(x0 - M);
            float p1 = __expf(x1 - M);
            Ss[r * 68 + lane]      = p0;
            Ss[r * 68 + 32 + lane] = p1;
            float sum = p0 + p1;
#pragma unroll
            for (int off = 16; off > 0; off >>= 1)
                sum += __shfl_xor_sync(0xffffffffu, sum, off);
            if (lane == 0) {
                float corr = __expf(mo - M);
                l_s[r] = l_s[r] * corr + sum;
                m_s[r] = M;
                c_s[r] = corr;
            }
        }
        __syncthreads();

        // ---- rescale O, then O += P @ V ----
        float cr[4];
#pragma unroll
        for (int i = 0; i < 4; i++) cr[i] = c_s[ty * 4 + i];
#pragma unroll
        for (int i = 0; i < 4; i++)
#pragma unroll
            for (int j = 0; j < 8; j++) o[i][j] *= cr[i];

#pragma unroll 4
        for (int ki = 0; ki < 64; ki++) {
            float p0 = Ss[(ty * 4 + 0) * 68 + ki];
            float p1 = Ss[(ty * 4 + 1) * 68 + ki];
            float p2 = Ss[(ty * 4 + 2) * 68 + ki];
            float p3 = Ss[(ty * 4 + 3) * 68 + ki];
            float4 v0 = *reinterpret_cast<const float4*>(&Vs[ki * 128 + tx * 4]);
            float4 v1 = *reinterpret_cast<const float4*>(&Vs[ki * 128 + 64 + tx * 4]);
            float vr[8] = {v0.x, v0.y, v0.z, v0.w, v1.x, v1.y, v1.z, v1.w};
            float pr[4] = {p0, p1, p2, p3};
#pragma unroll
            for (int i = 0; i < 4; i++)
#pragma unroll
                for (int j = 0; j < 8; j++)
                    o[i][j] = fmaf(pr[i], vr[j], o[i][j]);
        }
        __syncthreads();
    }

    // ---- epilogue: divide by l, write merged-head layout ----
#pragma unroll
    for (int i = 0; i < 4; i++) {
        int r = ty * 4 + i;
        float inv = 1.f / l_s[r];
        float* orow = out + ((size_t)b * SEQ + (q0 + r)) * EMBED + h * HDIM;
        float4 o0, o1;
        o0.x = o[i][0] * inv; o0.y = o[i][1] * inv;
        o0.z = o[i][2] * inv; o0.w = o[i][3] * inv;
        o1.x = o[i][4] * inv; o1.y = o[i][5] * inv;
        o1.z = o[i][6] * inv; o1.w = o[i][7] * inv;
        *reinterpret_cast<float4*>(orow + tx * 4)      = o0;
        *reinterpret_cast<float4*>(orow + 64 + tx * 4) = o1;
    }
}

// ---------------------------------------------------------------------------
// Launch: GEMM1 (QKV) -> attention -> GEMM2 (proj). Same stream, capturable.
// ---------------------------------------------------------------------------
extern "C" void kernel_launch(void* const* d_in, const int* in_sizes, int n_in,
                              void* d_out, int out_size)
{
    const float* x     = (const float*)d_in[0];   // [4,2048,1024]
    const float* Wqkv  = (const float*)d_in[1];   // [1024,3072]
    const float* bqkv  = (const float*)d_in[2];   // [3072]
    const float* Wproj = (const float*)d_in[3];   // [1024,1024]
    const float* bproj = (const float*)d_in[4];   // [1024]
    float* out = (float*)d_out;

    void* p_qkv = nullptr;
    void* p_att = nullptr;
    cudaGetSymbolAddress(&p_qkv, g_qkv);
    cudaGetSymbolAddress(&p_att, g_att);
    float* qkv = (float*)p_qkv;
    float* att = (float*)p_att;

    // GEMM1: [8192,1024] @ [1024,3072] + b -> qkv
    sgemm_bias_kernel<<<dim3(QKV_N / 128, MROWS / 128), 256>>>(
        x, Wqkv, bqkv, qkv, MROWS, QKV_N, EMBED);

    // Attention
    cudaFuncSetAttribute(attention_kernel,
                         cudaFuncAttributeMaxDynamicSharedMemorySize,
                         FA_SMEM_BYTES);
    attention_kernel<<<dim3(SEQ / 64, HEADS, BATCH), 256, FA_SMEM_BYTES>>>(
        qkv, att);

    // GEMM2: [8192,1024] @ [1024,1024] + b -> out
    sgemm_bias_kernel<<<dim3(EMBED / 128, MROWS / 128), 256>>>(
        att, Wproj, bproj, out, MROWS, EMBED, EMBED);
}